// round 15
// baseline (speedup 1.0000x reference)
#include <cuda_runtime.h>

#define BB 64
#define CC 512
#define HH 28
#define WW 28
#define HWSZ (HH*WW)
#define HID 32
#define NPLANE (BB*CC)
#define NLAYERS 4
#define QPP 196            // float4 quads per plane
#define PPB 8              // planes per block (1 warp each)
#define NUPD (NPLANE/PPB)  // 4096 update blocks
#define NSLOT 49           // stats per plane

// Scratch (static device memory -- allocation-free)
__device__ float g_st4[4][NSLOT * NPLANE];       // per-layer plane stats
__device__ float g_scaleArr[NLAYERS * NPLANE];   // all scales
__device__ int   g_ready[NLAYERS * BB];          // sticky flags (replay-safe by value identity)

__device__ __forceinline__ float sigmf(float x) { return 1.0f / (1.0f + __expf(-x)); }
__device__ __forceinline__ float tanhfast(float x) {
    float e = __expf(2.0f * x);
    return __fdividef(e - 1.0f, e + 1.0f);
}

// stat slot maps (rings 0..2 on each side)
__device__ __forceinline__ int rslot(int r) { return (r < 3) ? 1 + r : 4 + (r - 25); }
__device__ __forceinline__ int cslot(int c) { return (c < 3) ? 7 + c : 10 + (c - 25); }
__device__ __forceinline__ int pslot(int i, int j) {
    int bi = (i < 3) ? 0 : 1, ii = (i < 3) ? i : i - 25;
    int bj = (j < 3) ? 0 : 1, jj = (j < 3) ? j : j - 25;
    return 13 + (bi * 2 + bj) * 9 + ii * 3 + jj;
}

// ---------------- pool: float4-staged, warp-per-plane; emits 49 stats ----------------
__global__ void __launch_bounds__(256) k_pool(const float* __restrict__ x) {
    __shared__ __align__(16) float smem[PPB * HWSZ];
    int tid = threadIdx.x, lane = tid & 31, w = tid >> 5;
    int plane = blockIdx.x * PPB + w;
    float* sp = smem + w * HWSZ;
    const float4* in4 = (const float4*)(x + (size_t)plane * HWSZ);
    float4* sp4 = (float4*)sp;
    #pragma unroll
    for (int q = lane; q < QPP; q += 32) sp4[q] = in4[q];
    __syncwarp();

    float* st = g_st4[0];
    float cs = 0.f;
    #pragma unroll
    for (int y = 0; y < HH; y++) {
        float v = (lane < WW) ? sp[y * WW + lane] : 0.f;
        cs += v;
        if (y < 3 || y > 24) {
            float rs = v;
            #pragma unroll
            for (int o = 16; o; o >>= 1) rs += __shfl_down_sync(0xffffffffu, rs, o);
            if (lane == 0) st[rslot(y) * NPLANE + plane] = rs;
            if (lane < 3 || (lane > 24 && lane < WW)) st[pslot(y, lane) * NPLANE + plane] = v;
        }
    }
    if (lane < 3 || (lane > 24 && lane < WW)) st[cslot(lane) * NPLANE + plane] = cs;
    float T = cs;
    #pragma unroll
    for (int o = 16; o; o >>= 1) T += __shfl_down_sync(0xffffffffu, T, o);
    if (lane == 0) st[plane] = T;    // slot 0
}

// ---------------- analytic stat propagation (verified R13/R14) ----------------
template<int ROUT>
__device__ __forceinline__ void propagate(const float* __restrict__ stIn,
                                          float* __restrict__ stOut,
                                          int plane, float s, const float* wq) {
    float T = stIn[plane];
    float sc = 0.f;
    #pragma unroll
    for (int dy = -1; dy <= 1; dy++)
    #pragma unroll
    for (int dx = -1; dx <= 1; dx++) {
        float S = T;
        if (dy) S -= stIn[rslot(dy < 0 ? 27 : 0) * NPLANE + plane];
        if (dx) S -= stIn[cslot(dx < 0 ? 27 : 0) * NPLANE + plane];
        if (dy && dx) S += stIn[pslot(dy < 0 ? 27 : 0, dx < 0 ? 27 : 0) * NPLANE + plane];
        sc += wq[(dy + 1) * 3 + (dx + 1)] * S;
    }
    stOut[plane] = s * T + sc;

    #pragma unroll
    for (int ii = 0; ii < ROUT; ii++)
    #pragma unroll
    for (int side = 0; side < 2; side++) {
        int i = side ? 27 - ii : ii;
        float acc = s * stIn[rslot(i) * NPLANE + plane];
        #pragma unroll
        for (int dy = -1; dy <= 1; dy++) {
            int r = i + dy; if (r < 0 || r > 27) continue;
            float rv  = stIn[rslot(r) * NPLANE + plane];
            float p0  = stIn[pslot(r, 0) * NPLANE + plane];
            float p27 = stIn[pslot(r, 27) * NPLANE + plane];
            acc += wq[(dy + 1) * 3 + 0] * (rv - p27);
            acc += wq[(dy + 1) * 3 + 1] * rv;
            acc += wq[(dy + 1) * 3 + 2] * (rv - p0);
        }
        stOut[rslot(i) * NPLANE + plane] = acc;
    }
    #pragma unroll
    for (int jj = 0; jj < ROUT; jj++)
    #pragma unroll
    for (int side = 0; side < 2; side++) {
        int j = side ? 27 - jj : jj;
        float acc = s * stIn[cslot(j) * NPLANE + plane];
        #pragma unroll
        for (int dx = -1; dx <= 1; dx++) {
            int cc = j + dx; if (cc < 0 || cc > 27) continue;
            float cv = stIn[cslot(cc) * NPLANE + plane];
            float pt = stIn[pslot(0, cc) * NPLANE + plane];
            float pb = stIn[pslot(27, cc) * NPLANE + plane];
            acc += wq[0 * 3 + (dx + 1)] * (cv - pb);
            acc += wq[1 * 3 + (dx + 1)] * cv;
            acc += wq[2 * 3 + (dx + 1)] * (cv - pt);
        }
        stOut[cslot(j) * NPLANE + plane] = acc;
    }
    #pragma unroll
    for (int ii = 0; ii < ROUT; ii++)
    #pragma unroll
    for (int si = 0; si < 2; si++) {
        int i = si ? 27 - ii : ii;
        #pragma unroll
        for (int jj = 0; jj < ROUT; jj++)
        #pragma unroll
        for (int sj = 0; sj < 2; sj++) {
            int j = sj ? 27 - jj : jj;
            float acc = s * stIn[pslot(i, j) * NPLANE + plane];
            #pragma unroll
            for (int dy = -1; dy <= 1; dy++)
            #pragma unroll
            for (int dx = -1; dx <= 1; dx++) {
                int r = i + dy, cc = j + dx;
                if (r < 0 || r > 27 || cc < 0 || cc > 27) continue;
                acc += wq[(dy + 1) * 3 + (dx + 1)] * stIn[pslot(r, cc) * NPLANE + plane];
            }
            stOut[pslot(i, j) * NPLANE + plane] = acc;
        }
    }
}

// ---------------- prelude block body: 256 threads, batch b (+ redundant batch 0) ----------------
__device__ void prelude_block(int b, float* sm,
        const float* __restrict__ w_ih_l1, const float* __restrict__ b_ih_l1,
        const float* __restrict__ w_ih_l2, const float* __restrict__ b_ih_l2,
        const float* __restrict__ w_hh_l1, const float* __restrict__ b_hh_l1,
        const float* __restrict__ w_hh_l2, const float* __restrict__ b_hh_l2,
        const float* __restrict__ dw) {
    float* sseqB = sm;           // 512
    float* sseq0 = sm + 512;     // 512
    float* shtB  = sm + 1024;    // 512
    float* sht0  = sm + 1536;    // 512
    float* hidB  = sm + 2048;    // 64
    float* hid0  = sm + 2112;    // 64
    float* hid2  = sm + 2176;    // 32
    float* sgiB  = sm + 2208;    // 3*512
    float* sgi0  = sm + 3744;    // 3*512  (total 5280 <= PPB*HWSZ)
    int tid = threadIdx.x, lane = tid & 31, w = tid >> 5;  // 8 warps
    float ctB[2] = {0.f, 0.f}, ct0[2] = {0.f, 0.f};
    for (int i = tid; i < CC; i += 256) { shtB[i] = 0.f; sht0[i] = 0.f; }
    __syncthreads();

    for (int l = 0; l < NLAYERS; l++) {
        const float* stIn = g_st4[l];
        float* stOut = g_st4[(l < 3) ? l + 1 : 3];
        const float inv = 1.0f / HWSZ;
        for (int i = tid; i < CC; i += 256) {
            sseqB[i] = stIn[b * CC + i] * inv;
            if (b) sseq0[i] = stIn[i] * inv;
        }
        __syncthreads();

        // GEMVs for batch b: 64 dots of 512 (8 warps x 8)
        #pragma unroll
        for (int t = 0; t < 8; t++) {
            int d = w * 8 + t;
            int path = d >> 5, k = d & 31;
            const float4* wr4 = (const float4*)((path ? w_hh_l1 : w_ih_l1) + k * CC);
            const float4* in4 = (const float4*)(path ? shtB : sseqB);
            float s = 0.f;
            #pragma unroll
            for (int j = lane; j < 128; j += 32) {
                float4 wv = wr4[j], iv = in4[j];
                s += iv.x * wv.x + iv.y * wv.y + iv.z * wv.z + iv.w * wv.w;
            }
            #pragma unroll
            for (int o = 16; o; o >>= 1) s += __shfl_down_sync(0xffffffffu, s, o);
            if (lane == 0) hidB[d] = fmaxf(s + (path ? b_hh_l1 : b_ih_l1)[k], 0.f);
        }
        if (b) {
            #pragma unroll
            for (int t = 0; t < 8; t++) {
                int d = w * 8 + t;
                int path = d >> 5, k = d & 31;
                const float4* wr4 = (const float4*)((path ? w_hh_l1 : w_ih_l1) + k * CC);
                const float4* in4 = (const float4*)(path ? sht0 : sseq0);
                float s = 0.f;
                #pragma unroll
                for (int j = lane; j < 128; j += 32) {
                    float4 wv = wr4[j], iv = in4[j];
                    s += iv.x * wv.x + iv.y * wv.y + iv.z * wv.z + iv.w * wv.w;
                }
                #pragma unroll
                for (int o = 16; o; o >>= 1) s += __shfl_down_sync(0xffffffffu, s, o);
                if (lane == 0) hid0[d] = fmaxf(s + (path ? b_hh_l1 : b_ih_l1)[k], 0.f);
            }
        }
        __syncthreads();
        const float* h0 = b ? hid0 : hidB;

        // phase 2: 2 channels per thread
        #pragma unroll
        for (int half = 0; half < 2; half++) {
            int c = tid + half * 256;
            float giB[3], gi0[3], ghB[3], gh0[3];
            #pragma unroll
            for (int g = 0; g < 3; g++) {
                float bi2 = b_ih_l2[g * CC + c], bh2 = b_hh_l2[g * CC + c];
                const float4* wi4 = (const float4*)&w_ih_l2[(g * CC + c) * HID];
                const float4* wh4 = (const float4*)&w_hh_l2[(g * CC + c) * HID];
                float sB = 0.f, s0 = 0.f, tB = 0.f, t0 = 0.f;
                #pragma unroll
                for (int q = 0; q < 8; q++) {
                    float4 wi = wi4[q], wh = wh4[q];
                    int k = q * 4;
                    sB += hidB[k]*wi.x + hidB[k+1]*wi.y + hidB[k+2]*wi.z + hidB[k+3]*wi.w;
                    s0 += h0[k]*wi.x + h0[k+1]*wi.y + h0[k+2]*wi.z + h0[k+3]*wi.w;
                    tB += hidB[32+k]*wh.x + hidB[32+k+1]*wh.y + hidB[32+k+2]*wh.z + hidB[32+k+3]*wh.w;
                    t0 += h0[32+k]*wh.x + h0[32+k+1]*wh.y + h0[32+k+2]*wh.z + h0[32+k+3]*wh.w;
                }
                giB[g] = sB + bi2; gi0[g] = s0 + bi2;
                ghB[g] = tB + bh2; gh0[g] = t0 + bh2;
                sgiB[g * CC + c] = giB[g];
                sgi0[g * CC + c] = gi0[g];
            }
            {
                float ig = sigmf(giB[0] + ghB[0]);
                float fg = sigmf(giB[1] + ghB[1]);
                float cg = tanhfast(giB[2] + ghB[2]);
                ctB[half] = fg * ctB[half] + ig * cg;
                shtB[c] = sigmf(ctB[half]);
            }
            {
                float ig = sigmf(gi0[0] + gh0[0]);
                float fg = sigmf(gi0[1] + gh0[1]);
                float cg = tanhfast(gi0[2] + gh0[2]);
                ct0[half] = fg * ct0[half] + ig * cg;
                sht0[c] = sigmf(ct0[half]);
            }
        }
        __syncthreads();

        // hid2 = relu(W1h ht[0] + b1h): 32 dots (8 warps x 4)
        #pragma unroll
        for (int t = 0; t < 4; t++) {
            int k = w * 4 + t;
            const float4* wr4 = (const float4*)(w_hh_l1 + k * CC);
            float s = 0.f;
            #pragma unroll
            for (int j = lane; j < 128; j += 32) {
                float4 wv = wr4[j], iv = ((const float4*)sht0)[j];
                s += iv.x * wv.x + iv.y * wv.y + iv.z * wv.z + iv.w * wv.w;
            }
            #pragma unroll
            for (int o = 16; o; o >>= 1) s += __shfl_down_sync(0xffffffffu, s, o);
            if (lane == 0) hid2[k] = fmaxf(s + b_hh_l1[k], 0.f);
        }
        __syncthreads();

        // scales for both halves (keep for propagate), then publish, then propagate
        float sBv[2], s0v[2];
        #pragma unroll
        for (int half = 0; half < 2; half++) {
            int c = tid + half * 256;
            float gh2r[3];
            #pragma unroll
            for (int g = 0; g < 3; g++) {
                float acc = b_hh_l2[g * CC + c];
                const float4* wh4 = (const float4*)&w_hh_l2[(g * CC + c) * HID];
                #pragma unroll
                for (int q = 0; q < 8; q++) {
                    float4 wh = wh4[q];
                    int k = q * 4;
                    acc += hid2[k]*wh.x + hid2[k+1]*wh.y + hid2[k+2]*wh.z + hid2[k+3]*wh.w;
                }
                gh2r[g] = acc;
            }
            float i2 = sgiB[c] + gh2r[0];
            float f2 = sgiB[CC + c] + gh2r[1];
            float c2 = sgiB[2 * CC + c] + gh2r[2];
            sBv[half] = 1.0f + sigmf(sigmf(f2) * ct0[half] + sigmf(i2) * tanhfast(c2));
            g_scaleArr[l * NPLANE + b * CC + c] = sBv[half];
            s0v[half] = sBv[half];
            if (b) {
                float i0 = sgi0[c] + gh2r[0];
                float f0 = sgi0[CC + c] + gh2r[1];
                float c0 = sgi0[2 * CC + c] + gh2r[2];
                s0v[half] = 1.0f + sigmf(sigmf(f0) * ct0[half] + sigmf(i0) * tanhfast(c0));
                g_scaleArr[l * NPLANE + c] = s0v[half];   // identical across blocks: benign
            }
        }
        __syncthreads();
        if (tid == 0) { __threadfence(); atomicExch(&g_ready[l * BB + b], 1); }

        if (l < NLAYERS - 1) {
            #pragma unroll
            for (int half = 0; half < 2; half++) {
                int c = tid + half * 256;
                float wq[9];
                #pragma unroll
                for (int q = 0; q < 9; q++) wq[q] = dw[c * 9 + q];
                if (l == 0) {
                    propagate<2>(stIn, stOut, b * CC + c, sBv[half], wq);
                    if (b) propagate<2>(stIn, stOut, c, s0v[half], wq);
                } else if (l == 1) {
                    propagate<1>(stIn, stOut, b * CC + c, sBv[half], wq);
                    if (b) propagate<1>(stIn, stOut, c, s0v[half], wq);
                } else {
                    propagate<0>(stIn, stOut, b * CC + c, sBv[half], wq);
                    if (b) propagate<0>(stIn, stOut, c, s0v[half], wq);
                }
            }
        }
        __syncthreads();
    }
}

// ---------------- fused kernel: 64 prelude blocks + 4096 update blocks ----------------
__global__ void __launch_bounds__(256, 5) k_fused(
        const float* __restrict__ xin, float* __restrict__ xout,
        const float* __restrict__ dw,
        const float* __restrict__ w_ih_l1, const float* __restrict__ b_ih_l1,
        const float* __restrict__ w_ih_l2, const float* __restrict__ b_ih_l2,
        const float* __restrict__ w_hh_l1, const float* __restrict__ b_hh_l1,
        const float* __restrict__ w_hh_l2, const float* __restrict__ b_hh_l2) {
    __shared__ __align__(16) float smem[PPB * HWSZ + 32];

    if (blockIdx.x < BB) {
        prelude_block(blockIdx.x, smem,
                      w_ih_l1, b_ih_l1, w_ih_l2, b_ih_l2,
                      w_hh_l1, b_hh_l1, w_hh_l2, b_hh_l2, dw);
        return;
    }
    int pb = blockIdx.x - BB;
    int lane = threadIdx.x & 31, w = threadIdx.x >> 5;
    int plane = pb * PPB + w;
    int b = plane >> 9, c = plane & 511;
    float* sp = smem + w * HWSZ;

    // stage plane (overlaps with prelude compute)
    const float4* in4 = (const float4*)(xin + (size_t)plane * HWSZ);
    float4* sp4 = (float4*)sp;
    #pragma unroll
    for (int q = lane; q < QPP; q += 32) sp4[q] = in4[q];

    float wq[9];
    #pragma unroll
    for (int q = 0; q < 9; q++) wq[q] = dw[c * 9 + q];
    __syncwarp();

    int x = lane;
    bool active = x < WW;
    int xi = active ? x : 0;
    bool notL = (x > 0), notR = (x < WW - 1);

    #pragma unroll 1
    for (int p = 0; p < NLAYERS; p++) {
        float s;
        if (lane == 0) {
            while (__ldcg((const int*)&g_ready[p * BB + b]) == 0) __nanosleep(64);
            __threadfence();
            s = __ldcg(&g_scaleArr[p * NPLANE + plane]);
        }
        s = __shfl_sync(0xffffffffu, s, 0);

        float aL = 0.f, aC = 0.f, aR = 0.f;
        float bC = sp[xi];
        float bL = __shfl_up_sync(0xffffffffu, bC, 1);   if (!notL) bL = 0.f;
        float bR = __shfl_down_sync(0xffffffffu, bC, 1); if (!notR) bR = 0.f;
        float cC = sp[WW + xi];
        float cL = __shfl_up_sync(0xffffffffu, cC, 1);   if (!notL) cL = 0.f;
        float cR = __shfl_down_sync(0xffffffffu, cC, 1); if (!notR) cR = 0.f;
        #pragma unroll
        for (int y = 0; y < HH; y++) {
            float conv = wq[0] * aL + wq[1] * aC + wq[2] * aR
                       + wq[3] * bL + wq[4] * bC + wq[5] * bR
                       + wq[6] * cL + wq[7] * cC + wq[8] * cR;
            float o = fmaf(bC, s, conv);
            if (active) sp[y * WW + x] = o;     // in-place: writes trail reads by 2 rows
            aL = bL; aC = bC; aR = bR;
            bL = cL; bC = cC; bR = cR;
            if (y + 2 < HH) {
                cC = sp[(y + 2) * WW + xi];
                cL = __shfl_up_sync(0xffffffffu, cC, 1);   if (!notL) cL = 0.f;
                cR = __shfl_down_sync(0xffffffffu, cC, 1); if (!notR) cR = 0.f;
            } else { cC = cL = cR = 0.f; }
        }
        __syncwarp();
    }

    float4* out4 = (float4*)(xout + (size_t)plane * HWSZ);
    #pragma unroll
    for (int q = lane; q < QPP; q += 32) out4[q] = sp4[q];
}

extern "C" void kernel_launch(void* const* d_in, const int* in_sizes, int n_in,
                              void* d_out, int out_size) {
    const float* x        = (const float*)d_in[0];
    const float* w_ih_l1  = (const float*)d_in[1];
    const float* b_ih_l1  = (const float*)d_in[2];
    const float* w_ih_l2  = (const float*)d_in[3];
    const float* b_ih_l2  = (const float*)d_in[4];
    const float* w_hh_l1  = (const float*)d_in[5];
    const float* b_hh_l1  = (const float*)d_in[6];
    const float* w_hh_l2  = (const float*)d_in[7];
    const float* b_hh_l2  = (const float*)d_in[8];
    const float* dw       = (const float*)d_in[9];
    float* out = (float*)d_out;

    k_pool<<<NUPD, 256>>>(x);
    k_fused<<<BB + NUPD, 256>>>(x, out, dw,
                                w_ih_l1, b_ih_l1, w_ih_l2, b_ih_l2,
                                w_hh_l1, b_hh_l1, w_hh_l2, b_hh_l2);
}

// round 16
// speedup vs baseline: 1.4975x; 1.4975x over previous
#include <cuda_runtime.h>

#define BB 64
#define CC 512
#define HH 28
#define WW 28
#define HWSZ (HH*WW)
#define HID 32
#define NPLANE (BB*CC)
#define NLAYERS 4
#define QPP 196            // float4 quads per plane
#define PPB 8              // planes per block (1 warp each)
#define NUPD (NPLANE/PPB)  // 4096 blocks
#define NSLOT 49           // stats per plane

// Scratch (static device memory -- allocation-free)
__device__ float g_st0[NSLOT * NPLANE];          // layer-0 plane stats (from pool)
__device__ float g_scaleArr[NLAYERS * NPLANE];   // all scales, computed upfront

__device__ __forceinline__ float sigmf(float x) { return 1.0f / (1.0f + __expf(-x)); }
__device__ __forceinline__ float tanhfast(float x) {
    float e = __expf(2.0f * x);
    return __fdividef(e - 1.0f, e + 1.0f);
}

// stat slot maps (rings 0..2 on each side)
__device__ __forceinline__ int rslot(int r) { return (r < 3) ? 1 + r : 4 + (r - 25); }
__device__ __forceinline__ int cslot(int c) { return (c < 3) ? 7 + c : 10 + (c - 25); }
__device__ __forceinline__ int pslot(int i, int j) {
    int bi = (i < 3) ? 0 : 1, ii = (i < 3) ? i : i - 25;
    int bj = (j < 3) ? 0 : 1, jj = (j < 3) ? j : j - 25;
    return 13 + (bi * 2 + bj) * 9 + ii * 3 + jj;
}

// ---------------- pool: float4-staged, warp-per-plane; emits 49 stats (R15-verified) ----------------
__global__ void __launch_bounds__(256) k_pool(const float* __restrict__ x) {
    __shared__ __align__(16) float smem[PPB * HWSZ];
    int tid = threadIdx.x, lane = tid & 31, w = tid >> 5;
    int plane = blockIdx.x * PPB + w;
    float* sp = smem + w * HWSZ;
    const float4* in4 = (const float4*)(x + (size_t)plane * HWSZ);
    float4* sp4 = (float4*)sp;
    #pragma unroll
    for (int q = lane; q < QPP; q += 32) sp4[q] = in4[q];
    __syncwarp();

    float cs = 0.f;
    #pragma unroll
    for (int y = 0; y < HH; y++) {
        float v = (lane < WW) ? sp[y * WW + lane] : 0.f;
        cs += v;
        if (y < 3 || y > 24) {
            float rs = v;
            #pragma unroll
            for (int o = 16; o; o >>= 1) rs += __shfl_down_sync(0xffffffffu, rs, o);
            if (lane == 0) g_st0[rslot(y) * NPLANE + plane] = rs;
            if (lane < 3 || (lane > 24 && lane < WW)) g_st0[pslot(y, lane) * NPLANE + plane] = v;
        }
    }
    if (lane < 3 || (lane > 24 && lane < WW)) g_st0[cslot(lane) * NPLANE + plane] = cs;
    float T = cs;
    #pragma unroll
    for (int o = 16; o; o >>= 1) T += __shfl_down_sync(0xffffffffu, T, o);
    if (lane == 0) g_st0[plane] = T;    // slot 0
}

// ---------------- in-place smem stat propagation (math verified R13/R14) ----------------
// stp: smem stat column base (stride 512), c = channel. Reads old values of its
// OWN plane only, buffers outputs, writes back after all reads.
template<int ROUT>
__device__ __forceinline__ void propagateS(float* __restrict__ stp, int c,
                                           float s, const float* wq) {
    #define STIN(slot) stp[(slot) * 512 + c]
    float ovT;
    {
        float T = STIN(0);
        float sc = 0.f;
        #pragma unroll
        for (int dy = -1; dy <= 1; dy++)
        #pragma unroll
        for (int dx = -1; dx <= 1; dx++) {
            float S = T;
            if (dy) S -= STIN(rslot(dy < 0 ? 27 : 0));
            if (dx) S -= STIN(cslot(dx < 0 ? 27 : 0));
            if (dy && dx) S += STIN(pslot(dy < 0 ? 27 : 0, dx < 0 ? 27 : 0));
            sc += wq[(dy + 1) * 3 + (dx + 1)] * S;
        }
        ovT = s * T + sc;
    }
    float ovR[ROUT > 0 ? 2 * ROUT : 1], ovC[ROUT > 0 ? 2 * ROUT : 1];
    float ovP[ROUT > 0 ? 4 * ROUT * ROUT : 1];
    #pragma unroll
    for (int ii = 0; ii < ROUT; ii++)
    #pragma unroll
    for (int side = 0; side < 2; side++) {
        int i = side ? 27 - ii : ii;
        float acc = s * STIN(rslot(i));
        #pragma unroll
        for (int dy = -1; dy <= 1; dy++) {
            int r = i + dy; if (r < 0 || r > 27) continue;
            float rv  = STIN(rslot(r));
            float p0  = STIN(pslot(r, 0));
            float p27 = STIN(pslot(r, 27));
            acc += wq[(dy + 1) * 3 + 0] * (rv - p27);
            acc += wq[(dy + 1) * 3 + 1] * rv;
            acc += wq[(dy + 1) * 3 + 2] * (rv - p0);
        }
        ovR[ii * 2 + side] = acc;
    }
    #pragma unroll
    for (int jj = 0; jj < ROUT; jj++)
    #pragma unroll
    for (int side = 0; side < 2; side++) {
        int j = side ? 27 - jj : jj;
        float acc = s * STIN(cslot(j));
        #pragma unroll
        for (int dx = -1; dx <= 1; dx++) {
            int cc = j + dx; if (cc < 0 || cc > 27) continue;
            float cv = STIN(cslot(cc));
            float pt = STIN(pslot(0, cc));
            float pb = STIN(pslot(27, cc));
            acc += wq[0 * 3 + (dx + 1)] * (cv - pb);
            acc += wq[1 * 3 + (dx + 1)] * cv;
            acc += wq[2 * 3 + (dx + 1)] * (cv - pt);
        }
        ovC[jj * 2 + side] = acc;
    }
    #pragma unroll
    for (int ii = 0; ii < ROUT; ii++)
    #pragma unroll
    for (int si = 0; si < 2; si++) {
        int i = si ? 27 - ii : ii;
        #pragma unroll
        for (int jj = 0; jj < ROUT; jj++)
        #pragma unroll
        for (int sj = 0; sj < 2; sj++) {
            int j = sj ? 27 - jj : jj;
            float acc = s * STIN(pslot(i, j));
            #pragma unroll
            for (int dy = -1; dy <= 1; dy++)
            #pragma unroll
            for (int dx = -1; dx <= 1; dx++) {
                int r = i + dy, cc = j + dx;
                if (r < 0 || r > 27 || cc < 0 || cc > 27) continue;
                acc += wq[(dy + 1) * 3 + (dx + 1)] * STIN(pslot(r, cc));
            }
            ovP[((ii * 2 + si) * 2 * ROUT) + jj * 2 + sj] = acc;
        }
    }
    // write back
    STIN(0) = ovT;
    #pragma unroll
    for (int ii = 0; ii < ROUT; ii++)
    #pragma unroll
    for (int side = 0; side < 2; side++) {
        int i = side ? 27 - ii : ii;
        STIN(rslot(i)) = ovR[ii * 2 + side];
        STIN(cslot(i)) = ovC[ii * 2 + side];
    }
    #pragma unroll
    for (int ii = 0; ii < ROUT; ii++)
    #pragma unroll
    for (int si = 0; si < 2; si++) {
        int i = si ? 27 - ii : ii;
        #pragma unroll
        for (int jj = 0; jj < ROUT; jj++)
        #pragma unroll
        for (int sj = 0; sj < 2; sj++) {
            int j = sj ? 27 - jj : jj;
            STIN(pslot(i, j)) = ovP[((ii * 2 + si) * 2 * ROUT) + jj * 2 + sj];
        }
    }
    #undef STIN
}

// ---------------- prelude: 64 independent blocks (512 thr), all stats in smem ----------------
__global__ void __launch_bounds__(512) k_prelude(
        const float* __restrict__ w_ih_l1, const float* __restrict__ b_ih_l1,
        const float* __restrict__ w_ih_l2, const float* __restrict__ b_ih_l2,
        const float* __restrict__ w_hh_l1, const float* __restrict__ b_hh_l1,
        const float* __restrict__ w_hh_l2, const float* __restrict__ b_hh_l2,
        const float* __restrict__ dw) {
    extern __shared__ __align__(16) float dyn[];
    float* stB   = dyn;                    // 49*512
    float* st0   = dyn + NSLOT * 512;      // 49*512
    float* sseqB = dyn + 2 * NSLOT * 512;  // 512
    float* sseq0 = sseqB + 512;            // 512
    float* shtB  = sseq0 + 512;            // 512
    float* sht0  = shtB + 512;             // 512
    float* hidB  = sht0 + 512;             // 64
    float* hid0  = hidB + 64;              // 64
    float* hid2  = hid0 + 64;              // 32

    int b = blockIdx.x, tid = threadIdx.x, lane = tid & 31, w = tid >> 5;  // 16 warps
    int c = tid;
    float ctB = 0.f, ct0 = 0.f;
    shtB[c] = 0.f; sht0[c] = 0.f;

    // load stats for own batch + batch 0 (coalesced)
    #pragma unroll
    for (int s = 0; s < NSLOT; s++) {
        stB[s * 512 + c] = g_st0[s * NPLANE + b * CC + c];
        st0[s * 512 + c] = g_st0[s * NPLANE + c];
    }
    float wq[9];
    #pragma unroll
    for (int q = 0; q < 9; q++) wq[q] = dw[c * 9 + q];
    __syncthreads();

    for (int l = 0; l < NLAYERS; l++) {
        const float inv = 1.0f / HWSZ;
        sseqB[c] = stB[c] * inv;       // slot 0
        sseq0[c] = st0[c] * inv;
        __syncthreads();

        // 128 dots of 512: warps 0-7 batch b, warps 8-15 batch 0
        {
            int isB0 = (w >= 8);
            const float* inI = isB0 ? sseq0 : sseqB;
            const float* inH = isB0 ? sht0 : shtB;
            float* outH = isB0 ? hid0 : hidB;
            int w8 = w & 7;
            #pragma unroll
            for (int t = 0; t < 8; t++) {
                int d = w8 * 8 + t;
                int path = d >> 5, k = d & 31;
                const float4* wr4 = (const float4*)((path ? w_hh_l1 : w_ih_l1) + k * CC);
                const float4* in4 = (const float4*)(path ? inH : inI);
                float s = 0.f;
                #pragma unroll
                for (int j = lane; j < 128; j += 32) {
                    float4 wv = wr4[j], iv = in4[j];
                    s += iv.x * wv.x + iv.y * wv.y + iv.z * wv.z + iv.w * wv.w;
                }
                #pragma unroll
                for (int o = 16; o; o >>= 1) s += __shfl_down_sync(0xffffffffu, s, o);
                if (lane == 0) outH[d] = fmaxf(s + (path ? b_hh_l1 : b_ih_l1)[k], 0.f);
            }
        }
        __syncthreads();

        // phase 2 gates for both batches, channel c = tid
        float giB[3], gi0[3], ghB[3], gh0[3];
        #pragma unroll
        for (int g = 0; g < 3; g++) {
            float bi2 = b_ih_l2[g * CC + c], bh2 = b_hh_l2[g * CC + c];
            const float4* wi4 = (const float4*)&w_ih_l2[(g * CC + c) * HID];
            const float4* wh4 = (const float4*)&w_hh_l2[(g * CC + c) * HID];
            float sB = 0.f, s0 = 0.f, tB = 0.f, t0 = 0.f;
            #pragma unroll
            for (int q = 0; q < 8; q++) {
                float4 wi = wi4[q], wh = wh4[q];
                int k = q * 4;
                sB += hidB[k]*wi.x + hidB[k+1]*wi.y + hidB[k+2]*wi.z + hidB[k+3]*wi.w;
                s0 += hid0[k]*wi.x + hid0[k+1]*wi.y + hid0[k+2]*wi.z + hid0[k+3]*wi.w;
                tB += hidB[32+k]*wh.x + hidB[32+k+1]*wh.y + hidB[32+k+2]*wh.z + hidB[32+k+3]*wh.w;
                t0 += hid0[32+k]*wh.x + hid0[32+k+1]*wh.y + hid0[32+k+2]*wh.z + hid0[32+k+3]*wh.w;
            }
            giB[g] = sB + bi2; gi0[g] = s0 + bi2;
            ghB[g] = tB + bh2; gh0[g] = t0 + bh2;
        }
        {
            float ig = sigmf(giB[0] + ghB[0]);
            float fg = sigmf(giB[1] + ghB[1]);
            float cg = tanhfast(giB[2] + ghB[2]);
            ctB = fg * ctB + ig * cg;
            shtB[c] = sigmf(ctB);
        }
        {
            float ig = sigmf(gi0[0] + gh0[0]);
            float fg = sigmf(gi0[1] + gh0[1]);
            float cg = tanhfast(gi0[2] + gh0[2]);
            ct0 = fg * ct0 + ig * cg;
            sht0[c] = sigmf(ct0);
        }
        __syncthreads();

        // hid2 = relu(W1h ht[0] + b1h): 32 dots (16 warps x 2)
        #pragma unroll
        for (int t = 0; t < 2; t++) {
            int k = w * 2 + t;
            const float4* wr4 = (const float4*)(w_hh_l1 + k * CC);
            float s = 0.f;
            #pragma unroll
            for (int j = lane; j < 128; j += 32) {
                float4 wv = wr4[j], iv = ((const float4*)sht0)[j];
                s += iv.x * wv.x + iv.y * wv.y + iv.z * wv.z + iv.w * wv.w;
            }
            #pragma unroll
            for (int o = 16; o; o >>= 1) s += __shfl_down_sync(0xffffffffu, s, o);
            if (lane == 0) hid2[k] = fmaxf(s + b_hh_l1[k], 0.f);
        }
        __syncthreads();

        // gh2 for own channel, then scales
        float gh2r[3];
        #pragma unroll
        for (int g = 0; g < 3; g++) {
            float acc = b_hh_l2[g * CC + c];
            const float4* wh4 = (const float4*)&w_hh_l2[(g * CC + c) * HID];
            #pragma unroll
            for (int q = 0; q < 8; q++) {
                float4 wh = wh4[q];
                int k = q * 4;
                acc += hid2[k]*wh.x + hid2[k+1]*wh.y + hid2[k+2]*wh.z + hid2[k+3]*wh.w;
            }
            gh2r[g] = acc;
        }
        float i2 = giB[0] + gh2r[0], f2 = giB[1] + gh2r[1], c2 = giB[2] + gh2r[2];
        float sB = 1.0f + sigmf(sigmf(f2) * ct0 + sigmf(i2) * tanhfast(c2));
        g_scaleArr[l * NPLANE + b * CC + c] = sB;
        float i0 = gi0[0] + gh2r[0], f0 = gi0[1] + gh2r[1], c0 = gi0[2] + gh2r[2];
        float s0v = 1.0f + sigmf(sigmf(f0) * ct0 + sigmf(i0) * tanhfast(c0));
        g_scaleArr[l * NPLANE + c] = s0v;   // identical across blocks: benign

        // in-place smem stat propagation (not needed after last layer)
        if (l == 0) {
            propagateS<2>(stB, c, sB, wq);
            propagateS<2>(st0, c, s0v, wq);
        } else if (l == 1) {
            propagateS<1>(stB, c, sB, wq);
            propagateS<1>(st0, c, s0v, wq);
        } else if (l == 2) {
            propagateS<0>(stB, c, sB, wq);
            propagateS<0>(st0, c, s0v, wq);
        }
        __syncthreads();
    }
}

// ---------------- fused 4-pass update (R14-verified): all passes in registers ----------------
__global__ void __launch_bounds__(256) k_update4(
        const float* __restrict__ xin, float* __restrict__ xout,
        const float* __restrict__ dw) {
    __shared__ __align__(16) float smem[PPB * HWSZ + 32];
    int lane = threadIdx.x & 31, w = threadIdx.x >> 5;
    int plane = blockIdx.x * PPB + w;
    int c = plane & 511;
    float* sp = smem + w * HWSZ;

    const float4* in4 = (const float4*)(xin + (size_t)plane * HWSZ);
    float4* sp4 = (float4*)sp;
    #pragma unroll
    for (int q = lane; q < QPP; q += 32) sp4[q] = in4[q];

    float wq[9];
    #pragma unroll
    for (int q = 0; q < 9; q++) wq[q] = dw[c * 9 + q];
    float sc[NLAYERS];
    #pragma unroll
    for (int p = 0; p < NLAYERS; p++) sc[p] = g_scaleArr[p * NPLANE + plane];
    __syncwarp();

    int x = lane;
    bool active = x < WW;
    int xi = active ? x : (WW - 1);
    bool notL = (x > 0), notR = (x < WW - 1);

    float col[HH];
    #pragma unroll
    for (int y = 0; y < HH; y++) col[y] = sp[y * WW + xi];

    #pragma unroll
    for (int p = 0; p < NLAYERS; p++) {
        float s = sc[p];
        float aL = 0.f, aC = 0.f, aR = 0.f;
        float bC = col[0];
        float bL = __shfl_up_sync(0xffffffffu, bC, 1);   if (!notL) bL = 0.f;
        float bR = __shfl_down_sync(0xffffffffu, bC, 1); if (!notR) bR = 0.f;
        float cC = col[1];
        float cL = __shfl_up_sync(0xffffffffu, cC, 1);   if (!notL) cL = 0.f;
        float cR = __shfl_down_sync(0xffffffffu, cC, 1); if (!notR) cR = 0.f;
        #pragma unroll
        for (int y = 0; y < HH; y++) {
            float conv = wq[0] * aL + wq[1] * aC + wq[2] * aR
                       + wq[3] * bL + wq[4] * bC + wq[5] * bR
                       + wq[6] * cL + wq[7] * cC + wq[8] * cR;
            float o = fmaf(bC, s, conv);
            aL = bL; aC = bC; aR = bR;
            bL = cL; bC = cC; bR = cR;
            col[y] = o;
            if (y + 2 < HH) {
                cC = col[y + 2];
                cL = __shfl_up_sync(0xffffffffu, cC, 1);   if (!notL) cL = 0.f;
                cR = __shfl_down_sync(0xffffffffu, cC, 1); if (!notR) cR = 0.f;
            } else { cC = cL = cR = 0.f; }
        }
    }

    #pragma unroll
    for (int y = 0; y < HH; y++) if (active) sp[y * WW + x] = col[y];
    __syncwarp();
    float4* out4 = (float4*)(xout + (size_t)plane * HWSZ);
    #pragma unroll
    for (int q = lane; q < QPP; q += 32) out4[q] = sp4[q];
}

extern "C" void kernel_launch(void* const* d_in, const int* in_sizes, int n_in,
                              void* d_out, int out_size) {
    const float* x        = (const float*)d_in[0];
    const float* w_ih_l1  = (const float*)d_in[1];
    const float* b_ih_l1  = (const float*)d_in[2];
    const float* w_ih_l2  = (const float*)d_in[3];
    const float* b_ih_l2  = (const float*)d_in[4];
    const float* w_hh_l1  = (const float*)d_in[5];
    const float* b_hh_l1  = (const float*)d_in[6];
    const float* w_hh_l2  = (const float*)d_in[7];
    const float* b_hh_l2  = (const float*)d_in[8];
    const float* dw       = (const float*)d_in[9];
    float* out = (float*)d_out;

    static int smemSet = 0;
    const int DYN = (2 * NSLOT * 512 + 4 * 512 + 160) * 4;   // ~209 KB
    if (!smemSet) {
        cudaFuncSetAttribute(k_prelude, cudaFuncAttributeMaxDynamicSharedMemorySize, DYN);
        smemSet = 1;
    }

    k_pool<<<NUPD, 256>>>(x);
    k_prelude<<<BB, 512, DYN>>>(w_ih_l1, b_ih_l1, w_ih_l2, b_ih_l2,
                                w_hh_l1, b_hh_l1, w_hh_l2, b_hh_l2, dw);
    k_update4<<<NUPD, 256>>>(x, out, dw);
}

// round 17
// speedup vs baseline: 1.7733x; 1.1842x over previous
#include <cuda_runtime.h>

#define BB 64
#define CC 512
#define HH 28
#define WW 28
#define HWSZ (HH*WW)
#define HID 32
#define NPLANE (BB*CC)
#define NLAYERS 4
#define QPP 196            // float4 quads per plane
#define PPB 8              // planes per block (1 warp each)
#define NUP (NPLANE/PPB)   // 4096 update blocks
#define NSLOT 49           // stats per plane

// Scratch (static device memory -- allocation-free)
__device__ float g_st4[4][NSLOT * NPLANE];       // per-layer plane stats (no aliasing)
__device__ float g_scaleArr[NLAYERS * NPLANE];   // all scales, computed upfront

__device__ __forceinline__ float sigmf(float x) { return 1.0f / (1.0f + __expf(-x)); }
__device__ __forceinline__ float tanhfast(float x) {
    float e = __expf(2.0f * x);
    return __fdividef(e - 1.0f, e + 1.0f);
}

// ---- packed f32x2 helpers (sm_103a FFMA2 path) ----
typedef unsigned long long u64;
__device__ __forceinline__ u64 pk2(float lo, float hi) {
    u64 r; asm("mov.b64 %0, {%1, %2};" : "=l"(r) : "f"(lo), "f"(hi)); return r;
}
__device__ __forceinline__ void upk2(u64 v, float& lo, float& hi) {
    asm("mov.b64 {%0, %1}, %2;" : "=f"(lo), "=f"(hi) : "l"(v));
}
__device__ __forceinline__ u64 fma2(u64 a, u64 b, u64 c) {
    u64 d; asm("fma.rn.f32x2 %0, %1, %2, %3;" : "=l"(d) : "l"(a), "l"(b), "l"(c)); return d;
}
__device__ __forceinline__ u64 mul2(u64 a, u64 b) {
    u64 d; asm("mul.rn.f32x2 %0, %1, %2;" : "=l"(d) : "l"(a), "l"(b)); return d;
}

// stat slot maps (rings 0..2 on each side)
__device__ __forceinline__ int rslot(int r) { return (r < 3) ? 1 + r : 4 + (r - 25); }
__device__ __forceinline__ int cslot(int c) { return (c < 3) ? 7 + c : 10 + (c - 25); }
__device__ __forceinline__ int pslot(int i, int j) {
    int bi = (i < 3) ? 0 : 1, ii = (i < 3) ? i : i - 25;
    int bj = (j < 3) ? 0 : 1, jj = (j < 3) ? j : j - 25;
    return 13 + (bi * 2 + bj) * 9 + ii * 3 + jj;
}

// ---------------- pool: warp-per-plane; emits 49 stats (R14-verified) ----------------
__global__ void __launch_bounds__(256) k_pool(const float* __restrict__ x) {
    int tid = threadIdx.x, lane = tid & 31, w = tid >> 5;
    int plane = blockIdx.x * PPB + w;
    const float* p = x + (size_t)plane * HWSZ;
    float* st = g_st4[0];
    float cs = 0.f;
    #pragma unroll
    for (int y = 0; y < HH; y++) {
        float v = (lane < WW) ? p[y * WW + lane] : 0.f;
        cs += v;
        if (y < 3 || y > 24) {
            float rs = v;
            #pragma unroll
            for (int o = 16; o; o >>= 1) rs += __shfl_down_sync(0xffffffffu, rs, o);
            if (lane == 0) st[rslot(y) * NPLANE + plane] = rs;
            if (lane < 3 || (lane > 24 && lane < WW)) st[pslot(y, lane) * NPLANE + plane] = v;
        }
    }
    if (lane < 3 || (lane > 24 && lane < WW)) st[cslot(lane) * NPLANE + plane] = cs;
    float T = cs;
    #pragma unroll
    for (int o = 16; o; o >>= 1) T += __shfl_down_sync(0xffffffffu, T, o);
    if (lane == 0) st[plane] = T;    // slot 0
}

// ---------------- analytic stat propagation (R14-verified) ----------------
template<int ROUT>
__device__ __forceinline__ void propagate(const float* __restrict__ stIn,
                                          float* __restrict__ stOut,
                                          int plane, float s, const float* wq) {
    float T = stIn[plane];
    float sc = 0.f;
    #pragma unroll
    for (int dy = -1; dy <= 1; dy++)
    #pragma unroll
    for (int dx = -1; dx <= 1; dx++) {
        float S = T;
        if (dy) S -= stIn[rslot(dy < 0 ? 27 : 0) * NPLANE + plane];
        if (dx) S -= stIn[cslot(dx < 0 ? 27 : 0) * NPLANE + plane];
        if (dy && dx) S += stIn[pslot(dy < 0 ? 27 : 0, dx < 0 ? 27 : 0) * NPLANE + plane];
        sc += wq[(dy + 1) * 3 + (dx + 1)] * S;
    }
    stOut[plane] = s * T + sc;

    #pragma unroll
    for (int ii = 0; ii < ROUT; ii++)
    #pragma unroll
    for (int side = 0; side < 2; side++) {
        int i = side ? 27 - ii : ii;
        float acc = s * stIn[rslot(i) * NPLANE + plane];
        #pragma unroll
        for (int dy = -1; dy <= 1; dy++) {
            int r = i + dy; if (r < 0 || r > 27) continue;
            float rv  = stIn[rslot(r) * NPLANE + plane];
            float p0  = stIn[pslot(r, 0) * NPLANE + plane];
            float p27 = stIn[pslot(r, 27) * NPLANE + plane];
            acc += wq[(dy + 1) * 3 + 0] * (rv - p27);
            acc += wq[(dy + 1) * 3 + 1] * rv;
            acc += wq[(dy + 1) * 3 + 2] * (rv - p0);
        }
        stOut[rslot(i) * NPLANE + plane] = acc;
    }
    #pragma unroll
    for (int jj = 0; jj < ROUT; jj++)
    #pragma unroll
    for (int side = 0; side < 2; side++) {
        int j = side ? 27 - jj : jj;
        float acc = s * stIn[cslot(j) * NPLANE + plane];
        #pragma unroll
        for (int dx = -1; dx <= 1; dx++) {
            int cc = j + dx; if (cc < 0 || cc > 27) continue;
            float cv = stIn[cslot(cc) * NPLANE + plane];
            float pt = stIn[pslot(0, cc) * NPLANE + plane];
            float pb = stIn[pslot(27, cc) * NPLANE + plane];
            acc += wq[0 * 3 + (dx + 1)] * (cv - pb);
            acc += wq[1 * 3 + (dx + 1)] * cv;
            acc += wq[2 * 3 + (dx + 1)] * (cv - pt);
        }
        stOut[cslot(j) * NPLANE + plane] = acc;
    }
    #pragma unroll
    for (int ii = 0; ii < ROUT; ii++)
    #pragma unroll
    for (int si = 0; si < 2; si++) {
        int i = si ? 27 - ii : ii;
        #pragma unroll
        for (int jj = 0; jj < ROUT; jj++)
        #pragma unroll
        for (int sj = 0; sj < 2; sj++) {
            int j = sj ? 27 - jj : jj;
            float acc = s * stIn[pslot(i, j) * NPLANE + plane];
            #pragma unroll
            for (int dy = -1; dy <= 1; dy++)
            #pragma unroll
            for (int dx = -1; dx <= 1; dx++) {
                int r = i + dy, cc = j + dx;
                if (r < 0 || r > 27 || cc < 0 || cc > 27) continue;
                acc += wq[(dy + 1) * 3 + (dx + 1)] * stIn[pslot(r, cc) * NPLANE + plane];
            }
            stOut[pslot(i, j) * NPLANE + plane] = acc;
        }
    }
}

// ---------------- prelude: 64 independent blocks (R14-verified) ----------------
__global__ void __launch_bounds__(512) k_prelude(
        const float* __restrict__ w_ih_l1, const float* __restrict__ b_ih_l1,
        const float* __restrict__ w_ih_l2, const float* __restrict__ b_ih_l2,
        const float* __restrict__ w_hh_l1, const float* __restrict__ b_hh_l1,
        const float* __restrict__ w_hh_l2, const float* __restrict__ b_hh_l2,
        const float* __restrict__ dw) {
    __shared__ __align__(16) float sseqB[CC], sseq0[CC], shtB[CC], sht0[CC];
    __shared__ __align__(16) float hidB[64], hid0[64], hid2[HID];
    int b = blockIdx.x, tid = threadIdx.x, lane = tid & 31, w = tid >> 5;  // 16 warps
    int c = tid;
    float ctB = 0.f, ct0r = 0.f;
    shtB[tid] = 0.f; sht0[tid] = 0.f;
    float wq[9];
    #pragma unroll
    for (int q = 0; q < 9; q++) wq[q] = dw[c * 9 + q];
    __syncthreads();

    for (int l = 0; l < NLAYERS; l++) {
        const float* stIn = g_st4[l];
        float* stOut = g_st4[(l < 3) ? l + 1 : 3];
        sseqB[tid] = stIn[b * CC + tid] * (1.0f / HWSZ);
        if (b) sseq0[tid] = stIn[tid] * (1.0f / HWSZ);
        __syncthreads();

        {
            int isB0 = (w >= 8);
            if (!isB0 || b != 0) {
                const float* inI = isB0 ? sseq0 : sseqB;
                const float* inH = isB0 ? sht0 : shtB;
                float* outH = isB0 ? hid0 : hidB;
                int w8 = w & 7;
                #pragma unroll
                for (int t = 0; t < 8; t++) {
                    int d = w8 * 8 + t;
                    int path = d >> 5, k = d & 31;
                    const float4* wr4 = (const float4*)((path ? w_hh_l1 : w_ih_l1) + k * CC);
                    const float4* in4 = (const float4*)(path ? inH : inI);
                    float s = 0.f;
                    #pragma unroll
                    for (int j = lane; j < 128; j += 32) {
                        float4 wv = wr4[j], iv = in4[j];
                        s += iv.x * wv.x + iv.y * wv.y + iv.z * wv.z + iv.w * wv.w;
                    }
                    #pragma unroll
                    for (int o = 16; o; o >>= 1) s += __shfl_down_sync(0xffffffffu, s, o);
                    if (lane == 0) outH[d] = fmaxf(s + (path ? b_hh_l1 : b_ih_l1)[k], 0.f);
                }
            }
        }
        __syncthreads();
        const float* h0 = (b == 0) ? hidB : hid0;

        float giB[3], gi0[3], ghB[3], gh0[3];
        #pragma unroll
        for (int g = 0; g < 3; g++) {
            float bi2 = b_ih_l2[g * CC + c], bh2 = b_hh_l2[g * CC + c];
            const float4* wi4 = (const float4*)&w_ih_l2[(g * CC + c) * HID];
            const float4* wh4 = (const float4*)&w_hh_l2[(g * CC + c) * HID];
            float sB = 0.f, s0 = 0.f, tB = 0.f, t0 = 0.f;
            #pragma unroll
            for (int q = 0; q < 8; q++) {
                float4 wi = wi4[q], wh = wh4[q];
                int k = q * 4;
                sB += hidB[k]*wi.x + hidB[k+1]*wi.y + hidB[k+2]*wi.z + hidB[k+3]*wi.w;
                s0 += h0[k]*wi.x + h0[k+1]*wi.y + h0[k+2]*wi.z + h0[k+3]*wi.w;
                tB += hidB[32+k]*wh.x + hidB[32+k+1]*wh.y + hidB[32+k+2]*wh.z + hidB[32+k+3]*wh.w;
                t0 += h0[32+k]*wh.x + h0[32+k+1]*wh.y + h0[32+k+2]*wh.z + h0[32+k+3]*wh.w;
            }
            giB[g] = sB + bi2; gi0[g] = s0 + bi2;
            ghB[g] = tB + bh2; gh0[g] = t0 + bh2;
        }
        {
            float ig = sigmf(giB[0] + ghB[0]);
            float fg = sigmf(giB[1] + ghB[1]);
            float cg = tanhfast(giB[2] + ghB[2]);
            ctB = fg * ctB + ig * cg;
            shtB[c] = sigmf(ctB);
        }
        {
            float ig = sigmf(gi0[0] + gh0[0]);
            float fg = sigmf(gi0[1] + gh0[1]);
            float cg = tanhfast(gi0[2] + gh0[2]);
            ct0r = fg * ct0r + ig * cg;
            sht0[c] = sigmf(ct0r);
        }
        __syncthreads();

        #pragma unroll
        for (int t = 0; t < 2; t++) {
            int k = w * 2 + t;
            const float4* wr4 = (const float4*)(w_hh_l1 + k * CC);
            float s = 0.f;
            #pragma unroll
            for (int j = lane; j < 128; j += 32) {
                float4 wv = wr4[j], iv = ((const float4*)sht0)[j];
                s += iv.x * wv.x + iv.y * wv.y + iv.z * wv.z + iv.w * wv.w;
            }
            #pragma unroll
            for (int o = 16; o; o >>= 1) s += __shfl_down_sync(0xffffffffu, s, o);
            if (lane == 0) hid2[k] = fmaxf(s + b_hh_l1[k], 0.f);
        }
        __syncthreads();

        float gh2r[3];
        #pragma unroll
        for (int g = 0; g < 3; g++) {
            float acc = b_hh_l2[g * CC + c];
            const float4* wh4 = (const float4*)&w_hh_l2[(g * CC + c) * HID];
            #pragma unroll
            for (int q = 0; q < 8; q++) {
                float4 wh = wh4[q];
                int k = q * 4;
                acc += hid2[k]*wh.x + hid2[k+1]*wh.y + hid2[k+2]*wh.z + hid2[k+3]*wh.w;
            }
            gh2r[g] = acc;
        }

        float i2 = giB[0] + gh2r[0], f2 = giB[1] + gh2r[1], c2 = giB[2] + gh2r[2];
        float sB = 1.0f + sigmf(sigmf(f2) * ct0r + sigmf(i2) * tanhfast(c2));
        g_scaleArr[l * NPLANE + b * CC + c] = sB;
        float s0v = sB;
        if (b) {
            float i0 = gi0[0] + gh2r[0], f0 = gi0[1] + gh2r[1], c0 = gi0[2] + gh2r[2];
            s0v = 1.0f + sigmf(sigmf(f0) * ct0r + sigmf(i0) * tanhfast(c0));
            g_scaleArr[l * NPLANE + c] = s0v;   // identical across blocks: benign
        }

        if (l == 0) {
            propagate<2>(stIn, stOut, b * CC + c, sB, wq);
            if (b) propagate<2>(stIn, stOut, c, s0v, wq);
        } else if (l == 1) {
            propagate<1>(stIn, stOut, b * CC + c, sB, wq);
            if (b) propagate<1>(stIn, stOut, c, s0v, wq);
        } else if (l == 2) {
            propagate<0>(stIn, stOut, b * CC + c, sB, wq);
            if (b) propagate<0>(stIn, stOut, c, s0v, wq);
        }
        __syncthreads();
    }
}

// ---------------- fused 4-pass update: packed f32x2 (rows y & y+14 together) ----------------
__global__ void __launch_bounds__(256) k_update4(
        const float* __restrict__ xin, float* __restrict__ xout,
        const float* __restrict__ dw) {
    __shared__ __align__(16) float smem[PPB * HWSZ + 32];
    int lane = threadIdx.x & 31, w = threadIdx.x >> 5;
    int plane = blockIdx.x * PPB + w;
    int c = plane & 511;
    float* sp = smem + w * HWSZ;

    const float4* in4 = (const float4*)(xin + (size_t)plane * HWSZ);
    float4* sp4 = (float4*)sp;
    #pragma unroll
    for (int q = lane; q < QPP; q += 32) sp4[q] = in4[q];

    u64 w2[9];
    #pragma unroll
    for (int q = 0; q < 9; q++) { float wv = dw[c * 9 + q]; w2[q] = pk2(wv, wv); }
    u64 s2[NLAYERS];
    #pragma unroll
    for (int p = 0; p < NLAYERS; p++) { float sv = g_scaleArr[p * NPLANE + plane]; s2[p] = pk2(sv, sv); }
    __syncwarp();

    int x = lane;
    bool active = x < WW;
    int xi = active ? x : (WW - 1);
    bool notL = (x > 0), notR = (x < WW - 1);

    // pack rows (y, y+14) into col2[y], y = 0..13
    u64 col2[14];
    #pragma unroll
    for (int y = 0; y < 14; y++) col2[y] = pk2(sp[y * WW + xi], sp[(y + 14) * WW + xi]);

    #pragma unroll
    for (int p = 0; p < NLAYERS; p++) {
        u64 sPk = s2[p];
        float lo13, hi13, lo0, hi0;
        upk2(col2[13], lo13, hi13);    // lo13 = original row 13
        upk2(col2[0], lo0, hi0);       // hi0  = original row 14 (saved before overwrite)
        float r14 = hi0;

        u64 aC = pk2(0.f, lo13);       // rows (-1 -> 0, 13)
        u64 bC = col2[0];              // rows (0, 14)
        u64 cC = col2[1];              // rows (1, 15)
        u64 aL = __shfl_up_sync(0xffffffffu, aC, 1);   if (!notL) aL = 0ULL;
        u64 aR = __shfl_down_sync(0xffffffffu, aC, 1); if (!notR) aR = 0ULL;
        u64 bL = __shfl_up_sync(0xffffffffu, bC, 1);   if (!notL) bL = 0ULL;
        u64 bR = __shfl_down_sync(0xffffffffu, bC, 1); if (!notR) bR = 0ULL;
        u64 cL = __shfl_up_sync(0xffffffffu, cC, 1);   if (!notL) cL = 0ULL;
        u64 cR = __shfl_down_sync(0xffffffffu, cC, 1); if (!notR) cR = 0ULL;

        #pragma unroll
        for (int y = 0; y < 14; y++) {
            u64 acc = mul2(w2[0], aL);
            acc = fma2(w2[1], aC, acc);
            acc = fma2(w2[2], aR, acc);
            acc = fma2(w2[3], bL, acc);
            acc = fma2(w2[4], bC, acc);
            acc = fma2(w2[5], bR, acc);
            acc = fma2(w2[6], cL, acc);
            acc = fma2(w2[7], cC, acc);
            acc = fma2(w2[8], cR, acc);
            u64 out = fma2(bC, sPk, acc);
            aL = bL; aC = bC; aR = bR;
            bL = cL; bC = cC; bR = cR;
            col2[y] = out;
            if (y + 2 < 14) {
                cC = col2[y + 2];
                cL = __shfl_up_sync(0xffffffffu, cC, 1);   if (!notL) cL = 0ULL;
                cR = __shfl_down_sync(0xffffffffu, cC, 1); if (!notR) cR = 0ULL;
            } else if (y + 2 == 14) {
                cC = pk2(r14, 0.f);    // rows (14, 28 -> 0)
                cL = __shfl_up_sync(0xffffffffu, cC, 1);   if (!notL) cL = 0ULL;
                cR = __shfl_down_sync(0xffffffffu, cC, 1); if (!notR) cR = 0ULL;
            } else {
                cC = 0ULL; cL = 0ULL; cR = 0ULL;
            }
        }
    }

    // unpack & coalesced write-back
    #pragma unroll
    for (int y = 0; y < 14; y++) {
        float lo, hi;
        upk2(col2[y], lo, hi);
        if (active) { sp[y * WW + x] = lo; sp[(y + 14) * WW + x] = hi; }
    }
    __syncwarp();
    float4* out4 = (float4*)(xout + (size_t)plane * HWSZ);
    #pragma unroll
    for (int q = lane; q < QPP; q += 32) out4[q] = sp4[q];
}

extern "C" void kernel_launch(void* const* d_in, const int* in_sizes, int n_in,
                              void* d_out, int out_size) {
    const float* x        = (const float*)d_in[0];
    const float* w_ih_l1  = (const float*)d_in[1];
    const float* b_ih_l1  = (const float*)d_in[2];
    const float* w_ih_l2  = (const float*)d_in[3];
    const float* b_ih_l2  = (const float*)d_in[4];
    const float* w_hh_l1  = (const float*)d_in[5];
    const float* b_hh_l1  = (const float*)d_in[6];
    const float* w_hh_l2  = (const float*)d_in[7];
    const float* b_hh_l2  = (const float*)d_in[8];
    const float* dw       = (const float*)d_in[9];
    float* out = (float*)d_out;

    k_pool<<<NUP, 256>>>(x);
    k_prelude<<<BB, 512>>>(w_ih_l1, b_ih_l1, w_ih_l2, b_ih_l2,
                           w_hh_l1, b_hh_l1, w_hh_l2, b_hh_l2, dw);
    k_update4<<<NUP, 256>>>(x, out, dw);
}